// round 17
// baseline (speedup 1.0000x reference)
#include <cuda_runtime.h>
#include <cuda_fp16.h>
#include <mma.h>
#include <cstdint>

using namespace nvcuda;

#define MAXN 500000
#define MAXE 500000
#define F 128

// ---------------- scratch (static device globals; no allocation) ----------------
__device__ __half g_h[(size_t)MAXN * F];    // h = x @ W (fp16)
__device__ __half g_acc[(size_t)MAXN * F];  // edge-sum accumulator (fp16)
__device__ float g_s[MAXN];                 // per-node dot with a_src
__device__ float g_d[MAXN];                 // per-node dot with a_dst
__device__ float g_alpha[MAXE];             // per-edge exp(logit)
__device__ float g_sum;                     // softmax denominator

// ---------------- small helpers ----------------
__device__ __forceinline__ float warpSum(float v) {
    #pragma unroll
    for (int o = 16; o > 0; o >>= 1) v += __shfl_xor_sync(0xFFFFFFFFu, v, o);
    return v;
}

// ---------------- K1: h = x @ W, persistent wmma-fp16, 2 CTAs/SM ----------------
// 256 threads, 8 warps = 4(M) x 2(N); warp tile 32x64 = 2x4 m16n16k16 frags.
// x loaded via LDG.128 -> cvt -> STS fp16; co-resident CTA's MMA hides latency.
// Handles the partial last tile with predicated guards (no separate tail kernel).
// Also zeroes g_acc (fire-and-forget). SMEM: 69632 bytes -> 2 CTAs/SM.
#define WH_LD 136
#define XH_LD 136
#define SW_HALFS   (128 * WH_LD)              // 17408
#define XH_HALFS   (128 * XH_LD)              // 17408
#define GSMEM_BYTES (SW_HALFS * 2 + XH_HALFS * 2)

__global__ __launch_bounds__(256, 2) void gemm_mma_kernel(const float* __restrict__ x,
                                                          const float* __restrict__ w,
                                                          int numTiles, int N) {
    extern __shared__ char smem_raw[];
    __half* sW  = reinterpret_cast<__half*>(smem_raw);
    __half* sXh = reinterpret_cast<__half*>(smem_raw + SW_HALFS * 2);
    const int tid = threadIdx.x;
    const int stride = gridDim.x;

    if (blockIdx.x == 0 && tid == 0) g_sum = 0.0f;

    // Zero g_acc: fire-and-forget streaming stores, drain behind compute.
    {
        uint4* a4 = reinterpret_cast<uint4*>(g_acc);
        size_t total = (size_t)N * 16;   // uint4 units (8 halfs each)
        const uint4 z = make_uint4(0u, 0u, 0u, 0u);
        for (size_t i = (size_t)blockIdx.x * 256 + tid; i < total; i += (size_t)stride * 256)
            a4[i] = z;
    }

    // Stage W (K x N row-major) once as fp16.
    #pragma unroll
    for (int i = 0; i < 16; i++) {
        int q = tid + i * 256;       // float4 id, 4096 total
        int k = q >> 5;
        int c4 = q & 31;
        float4 v = reinterpret_cast<const float4*>(w)[q];
        __half2 p0 = __floats2half2_rn(v.x, v.y);
        __half2 p1 = __floats2half2_rn(v.z, v.w);
        uint2 u;
        u.x = *reinterpret_cast<uint32_t*>(&p0);
        u.y = *reinterpret_cast<uint32_t*>(&p1);
        *reinterpret_cast<uint2*>(&sW[k * WH_LD + c4 * 4]) = u;
    }

    const int wid = tid >> 5;
    const int lane = tid & 31;
    const int warp_m = wid & 3;          // 0..3
    const int warp_n = wid >> 2;         // 0..1
    const int n0 = warp_n * 64;

    for (int t = blockIdx.x; t < numTiles; t += stride) {
        __syncthreads();    // prior epilogue readers done; sXh reusable as input tile

        // Load x tile (fp32, coalesced LDG.128, guarded), convert, store fp16.
        #pragma unroll
        for (int i = 0; i < 16; i++) {
            int q = tid + i * 256;       // float4 id
            int r = q >> 5;
            int c4 = q & 31;
            int grow = t * 128 + r;
            float4 v = make_float4(0.f, 0.f, 0.f, 0.f);
            if (grow < N) v = reinterpret_cast<const float4*>(x)[(size_t)grow * 32 + c4];
            __half2 p0 = __floats2half2_rn(v.x, v.y);
            __half2 p1 = __floats2half2_rn(v.z, v.w);
            uint2 u;
            u.x = *reinterpret_cast<uint32_t*>(&p0);
            u.y = *reinterpret_cast<uint32_t*>(&p1);
            *reinterpret_cast<uint2*>(&sXh[r * XH_LD + c4 * 4]) = u;
        }
        __syncthreads();

        const __half* aBase = sXh + warp_m * 32 * XH_LD;

        wmma::fragment<wmma::accumulator, 16, 16, 16, float> c[2][4];
        #pragma unroll
        for (int mi = 0; mi < 2; mi++)
            #pragma unroll
            for (int ni = 0; ni < 4; ni++) wmma::fill_fragment(c[mi][ni], 0.0f);

        #pragma unroll
        for (int kf = 0; kf < 8; kf++) {
            const int k = kf * 16;
            wmma::fragment<wmma::matrix_a, 16, 16, 16, __half, wmma::row_major> a[2];
            wmma::fragment<wmma::matrix_b, 16, 16, 16, __half, wmma::row_major> b[4];
            #pragma unroll
            for (int mi = 0; mi < 2; mi++)
                wmma::load_matrix_sync(a[mi], aBase + mi * 16 * XH_LD + k, XH_LD);
            #pragma unroll
            for (int ni = 0; ni < 4; ni++)
                wmma::load_matrix_sync(b[ni], &sW[k * WH_LD + n0 + ni * 16], WH_LD);
            #pragma unroll
            for (int mi = 0; mi < 2; mi++)
                #pragma unroll
                for (int ni = 0; ni < 4; ni++)
                    wmma::mma_sync(c[mi][ni], a[mi], b[ni], c[mi][ni]);
        }

        __syncthreads();   // all warps done reading sXh; safe to reuse as staging

        // Epilogue: two 16-row waves through sXh-as-fp32 staging; 8B stores (guarded).
        float* myStg = reinterpret_cast<float*>(sXh) + wid * 1024;   // 16x64 fp32
        #pragma unroll
        for (int mi = 0; mi < 2; mi++) {
            #pragma unroll
            for (int ni = 0; ni < 4; ni++)
                wmma::store_matrix_sync(myStg + ni * 16, c[mi][ni], 64, wmma::mem_row_major);
            __syncwarp();
            const size_t m0 = (size_t)t * 128 + warp_m * 32 + mi * 16;
            const float2* stg2 = reinterpret_cast<const float2*>(myStg);
            const int rsub = lane >> 4;          // 0..1
            const int c2 = (lane & 15) * 2;      // float2 index within row
            #pragma unroll
            for (int rr = 0; rr < 16; rr += 2) {
                int r = rr + rsub;
                size_t grow = m0 + r;
                if (grow < (size_t)N) {
                    float2 va = stg2[r * 32 + c2];
                    float2 vb = stg2[r * 32 + c2 + 1];
                    __half2 h0 = __floats2half2_rn(va.x, va.y);
                    __half2 h1 = __floats2half2_rn(vb.x, vb.y);
                    uint2 u;
                    u.x = *reinterpret_cast<uint32_t*>(&h0);
                    u.y = *reinterpret_cast<uint32_t*>(&h1);
                    *reinterpret_cast<uint2*>(&g_h[grow * F + n0 + (lane & 15) * 4]) = u;
                }
            }
            __syncwarp();
        }
    }
}

// ---------------- K2: acc[row[e]] += h[col[e]]  (fp16 vector atomics) ----------------
__global__ __launch_bounds__(256) void scatter_kernel(const int* __restrict__ ei, int E) {
    int e = (blockIdx.x * blockDim.x + threadIdx.x) >> 5;
    int lane = threadIdx.x & 31;
    if (e >= E) return;
    int r = ei[e];
    int c = ei[E + e];
    uint2 pk = reinterpret_cast<const uint2*>(&g_h[(size_t)c * F])[lane];  // 4 halfs
    __half* dst = &g_acc[(size_t)r * F + lane * 4];
    asm volatile("red.global.add.noftz.v2.f16x2 [%0], {%1,%2};"
                 :: "l"(dst), "r"(pk.x), "r"(pk.y)
                 : "memory");
}

// ---------------- K3: s[i], d[i] from relu(acc+bias) — thread per node, no shfl -----
__global__ __launch_bounds__(256) void postproc_kernel(const float* __restrict__ bias,
                                                       const float* __restrict__ att,
                                                       int N) {
    __shared__ float sb[F], sas[F], sad[F];
    int tid = threadIdx.x;
    if (tid < F) {
        sb[tid]  = bias[tid];
        sas[tid] = att[tid];
        sad[tid] = att[F + tid];
    }
    __syncthreads();
    int node = blockIdx.x * blockDim.x + tid;
    if (node >= N) return;
    const uint4* row = reinterpret_cast<const uint4*>(&g_acc[(size_t)node * F]);
    float ss = 0.f, dd = 0.f;
    #pragma unroll
    for (int k = 0; k < 16; k++) {
        uint4 u = row[k];
        int b0 = k * 8;
        float2 f;
        float v0, v1;
        f = __half22float2(*reinterpret_cast<__half2*>(&u.x));
        v0 = fmaxf(f.x + sb[b0 + 0], 0.f); v1 = fmaxf(f.y + sb[b0 + 1], 0.f);
        ss += v0 * sas[b0 + 0] + v1 * sas[b0 + 1];
        dd += v0 * sad[b0 + 0] + v1 * sad[b0 + 1];
        f = __half22float2(*reinterpret_cast<__half2*>(&u.y));
        v0 = fmaxf(f.x + sb[b0 + 2], 0.f); v1 = fmaxf(f.y + sb[b0 + 3], 0.f);
        ss += v0 * sas[b0 + 2] + v1 * sas[b0 + 3];
        dd += v0 * sad[b0 + 2] + v1 * sad[b0 + 3];
        f = __half22float2(*reinterpret_cast<__half2*>(&u.z));
        v0 = fmaxf(f.x + sb[b0 + 4], 0.f); v1 = fmaxf(f.y + sb[b0 + 5], 0.f);
        ss += v0 * sas[b0 + 4] + v1 * sas[b0 + 5];
        dd += v0 * sad[b0 + 4] + v1 * sad[b0 + 5];
        f = __half22float2(*reinterpret_cast<__half2*>(&u.w));
        v0 = fmaxf(f.x + sb[b0 + 6], 0.f); v1 = fmaxf(f.y + sb[b0 + 7], 0.f);
        ss += v0 * sas[b0 + 6] + v1 * sas[b0 + 7];
        dd += v0 * sad[b0 + 6] + v1 * sad[b0 + 7];
    }
    g_s[node] = ss;
    g_d[node] = dd;
}

// ---------------- K4: alpha[e]=exp(leaky_relu(s[row]+d[col])); 4 edges/thread -------
// Unstable softmax (no max subtraction): logits are small dot products, |logit| << 88,
// so exp cannot overflow; result is mathematically identical to max-shifted softmax.
__global__ __launch_bounds__(256) void alpha_exp_kernel(const int* __restrict__ ei, int E) {
    int e0 = (blockIdx.x * blockDim.x + threadIdx.x) * 4;
    int lane = threadIdx.x & 31;
    int wid = threadIdx.x >> 5;
    float evs = 0.f;
    if (e0 + 3 < E) {
        int4 rr = *reinterpret_cast<const int4*>(&ei[e0]);
        int4 cc = *reinterpret_cast<const int4*>(&ei[E + e0]);
        float v0 = g_s[rr.x] + g_d[cc.x];
        float v1 = g_s[rr.y] + g_d[cc.y];
        float v2 = g_s[rr.z] + g_d[cc.z];
        float v3 = g_s[rr.w] + g_d[cc.w];
        v0 = (v0 > 0.f) ? v0 : 0.2f * v0;
        v1 = (v1 > 0.f) ? v1 : 0.2f * v1;
        v2 = (v2 > 0.f) ? v2 : 0.2f * v2;
        v3 = (v3 > 0.f) ? v3 : 0.2f * v3;
        float4 ev = make_float4(__expf(v0), __expf(v1), __expf(v2), __expf(v3));
        *reinterpret_cast<float4*>(&g_alpha[e0]) = ev;
        evs = ev.x + ev.y + ev.z + ev.w;
    } else if (e0 < E) {
        for (int j = 0; j < 4 && e0 + j < E; j++) {
            int r = ei[e0 + j];
            int c = ei[E + e0 + j];
            float v = g_s[r] + g_d[c];
            v = (v > 0.f) ? v : 0.2f * v;
            float ev = __expf(v);
            g_alpha[e0 + j] = ev;
            evs += ev;
        }
    }
    __shared__ float ssum[8];
    float s = warpSum(evs);
    if (lane == 0) ssum[wid] = s;
    __syncthreads();
    if (wid == 0) {
        float t = (lane < 8) ? ssum[lane] : 0.f;
        t = warpSum(t);
        if (lane == 0) atomicAdd(&g_sum, t);
    }
}

// ---------------- K5: out[i,:] = relu(acc[i,:]+bias) * alpha[i]/sum ----------------
__global__ __launch_bounds__(256) void scale_kernel(float* __restrict__ out,
                                                    const float* __restrict__ bias,
                                                    int N) {
    size_t i = (size_t)blockIdx.x * blockDim.x + threadIdx.x;  // float4 index
    if (i >= (size_t)N * 32) return;
    int node = (int)(i >> 5);
    float sc = g_alpha[node] / g_sum;
    uint2 pk = reinterpret_cast<const uint2*>(g_acc)[i];
    float2 f0 = __half22float2(*reinterpret_cast<__half2*>(&pk.x));
    float2 f1 = __half22float2(*reinterpret_cast<__half2*>(&pk.y));
    float4 b = reinterpret_cast<const float4*>(bias)[i & 31];
    float4 v;
    v.x = fmaxf(f0.x + b.x, 0.f) * sc;
    v.y = fmaxf(f0.y + b.y, 0.f) * sc;
    v.z = fmaxf(f1.x + b.z, 0.f) * sc;
    v.w = fmaxf(f1.y + b.w, 0.f) * sc;
    reinterpret_cast<float4*>(out)[i] = v;
}

extern "C" void kernel_launch(void* const* d_in, const int* in_sizes, int n_in,
                              void* d_out, int out_size) {
    const float* x   = (const float*)d_in[0];
    const int* ei    = (const int*)d_in[1];     // edge_index: int32
    const float* w   = (const float*)d_in[2];
    const float* att = (const float*)d_in[3];
    const float* bias= (const float*)d_in[4];
    float* out       = (float*)d_out;

    int N = in_sizes[0] / F;   // 500000
    int E = in_sizes[1] / 2;   // 500000

    static int smem_set = 0;
    if (!smem_set) {
        cudaFuncSetAttribute(gemm_mma_kernel, cudaFuncAttributeMaxDynamicSharedMemorySize, GSMEM_BYTES);
        smem_set = 1;
    }

    int numTiles = (N + 127) / 128;    // 3907 (last tile partial, guarded)
    int gemmGrid = 304;                // 2 CTAs/SM on 152 SMs
    if (gemmGrid > numTiles) gemmGrid = numTiles;

    gemm_mma_kernel<<<gemmGrid, 256, GSMEM_BYTES>>>(x, w, numTiles, N);
    scatter_kernel<<<(E + 7) / 8, 256>>>(ei, E);
    postproc_kernel<<<(N + 255) / 256, 256>>>(bias, att, N);
    alpha_exp_kernel<<<((E + 3) / 4 + 255) / 256, 256>>>(ei, E);
    scale_kernel<<<(int)(((size_t)N * 32 + 255) / 256), 256>>>(out, bias, N);
}